// round 1
// baseline (speedup 1.0000x reference)
#include <cuda_runtime.h>
#include <math.h>

// Problem constants (fixed by setup_inputs)
// B=32, N=64, ATTR=4, STATE=8, REL=4, GDIM=32, NF=128, pstep=2
#define NNODES 2048            // B*N
#define NF 128

// ---------------- scratch (static device memory; no allocations) ----------------
__device__ float g_rel[2048 * 128 * 64];   // rel_encode, layout [bi][f][j]  (64 MB)
__device__ float g_obj[2048 * 128];        // obj_encode (updated per step)
__device__ float g_u[2048 * 128];          // per-node recv part of re layer0 (incl b0)
__device__ float g_vt[32 * 128 * 64];      // per-node send part, layout [b][f][n]
__device__ float g_R[2048 * 128];          // W_recv @ obj + rp_b
__device__ float g_S[2048 * 128];          // W_send @ obj
__device__ float g_agg[2048 * 128];        // per-node aggregated edge effects
// transposed weights ([k][f] layouts for coalesced per-f accumulation)
__device__ float g_w1toe[128 * 128];
__device__ float g_w1tre[128 * 128];
__device__ float g_wrt[128 * 128];
__device__ float g_wrecvt[128 * 128];
__device__ float g_wsendt[128 * 128];
__device__ float g_ppwt[256 * 128];
__device__ float g_prw0t[128 * 128];
__device__ float g_prw1t[128 * 32];

// ---------------- weight prep: transposes ----------------
__global__ void prep_kernel(const float* __restrict__ oe_w1,
                            const float* __restrict__ re_w1,
                            const float* __restrict__ rp_w,
                            const float* __restrict__ pp_w,
                            const float* __restrict__ pr_w0,
                            const float* __restrict__ pr_w1) {
    int m = blockIdx.x;
    int t = threadIdx.x;
    if (m == 0) {
        for (int i = t; i < 128 * 128; i += 256) {
            int k = i >> 7, f = i & 127;
            g_w1toe[i] = oe_w1[f * 128 + k];
        }
    } else if (m == 1) {
        for (int i = t; i < 128 * 128; i += 256) {
            int k = i >> 7, f = i & 127;
            g_w1tre[i] = re_w1[f * 128 + k];
        }
    } else if (m == 2) {
        for (int i = t; i < 128 * 128; i += 256) {
            int k = i >> 7, f = i & 127;
            g_wrt[i] = rp_w[f * 384 + k];
        }
    } else if (m == 3) {
        for (int i = t; i < 128 * 128; i += 256) {
            int k = i >> 7, f = i & 127;
            g_wrecvt[i] = rp_w[f * 384 + 128 + k];
        }
    } else if (m == 4) {
        for (int i = t; i < 128 * 128; i += 256) {
            int k = i >> 7, f = i & 127;
            g_wsendt[i] = rp_w[f * 384 + 256 + k];
        }
    } else if (m == 5) {
        for (int i = t; i < 256 * 128; i += 256) {
            int k = i >> 7, f = i & 127;
            g_ppwt[i] = pp_w[f * 256 + k];
        }
    } else if (m == 6) {
        for (int i = t; i < 128 * 128; i += 256) {
            int k = i >> 7, f = i & 127;
            g_prw0t[i] = pr_w0[f * 128 + k];
        }
    } else {
        for (int i = t; i < 128 * 32; i += 256) {
            int k = i >> 5, o = i & 31;
            g_prw1t[i] = pr_w1[o * 128 + k];
        }
    }
}

// ---------------- per-node parts of rel layer0: u (recv) and v (send) ----------------
__global__ void node_pre_kernel(const float* __restrict__ attrs,
                                const float* __restrict__ states,
                                const float* __restrict__ re_w0,
                                const float* __restrict__ re_b0) {
    int node = blockIdx.x;
    int f = threadIdx.x;
    __shared__ float sa[4];
    __shared__ float ss[8];
    if (f < 4) sa[f] = attrs[node * 4 + f];
    if (f >= 4 && f < 12) ss[f - 4] = states[node * 8 + (f - 4)];
    __syncthreads();
    const float* w = re_w0 + f * 20;  // cols: [rel(4) | dstate(8) | recv_attr(4) | send_attr(4)]
    float u = re_b0[f];
    float v = 0.f;
#pragma unroll
    for (int c = 0; c < 8; c++) {
        float wc = w[4 + c];
        u += wc * ss[c];
        v -= wc * ss[c];
    }
#pragma unroll
    for (int c = 0; c < 4; c++) {
        u += w[12 + c] * sa[c];
        v += w[16 + c] * sa[c];
    }
    g_u[node * 128 + f] = u;
    int b = node >> 6, n = node & 63;
    g_vt[(b * 128 + f) * 64 + n] = v;
}

// ---------------- object encoder: 12 -> 128 -> 128, relu ----------------
__global__ void obj_encode_kernel(const float* __restrict__ attrs,
                                  const float* __restrict__ states,
                                  const float* __restrict__ oe_w0,
                                  const float* __restrict__ oe_b0,
                                  const float* __restrict__ oe_b1) {
    int node = blockIdx.x;
    int f = threadIdx.x;
    __shared__ float xs[12];
    __shared__ float hs[128];
    if (f < 4) xs[f] = attrs[node * 4 + f];
    if (f >= 4 && f < 12) xs[f] = states[node * 8 + (f - 4)];
    __syncthreads();
    const float* w = oe_w0 + f * 12;
    float h = oe_b0[f];
#pragma unroll
    for (int k = 0; k < 12; k++) h += w[k] * xs[k];
    hs[f] = fmaxf(h, 0.f);
    __syncthreads();
    float o = oe_b1[f];
#pragma unroll 16
    for (int k = 0; k < 128; k++) o += g_w1toe[k * 128 + f] * hs[k];
    g_obj[node * 128 + f] = fmaxf(o, 0.f);
}

// ---------------- relation encoder: per (b,i) block ----------------
// h0[k][j] = relu(W_rel . rel_attrs(b,i,j) + u[b,i][k] + v[b,j][k])
// rel[f][j] = relu(b1[f] + sum_k w1[f][k] * h0[k][j]) -> g_rel [bi][f][j]
__global__ __launch_bounds__(128) void rel_encode_kernel(const float* __restrict__ rel_attrs,
                                                         const float* __restrict__ re_w0,
                                                         const float* __restrict__ re_b1) {
    __shared__ float Hs[128 * 64];  // [k][j]
    __shared__ float Wc[16 * 128];  // [k][f] chunk
    __shared__ float Us[128];
    int bi = blockIdx.x;
    int tid = threadIdx.x;
    int b = bi >> 6;
    Us[tid] = g_u[bi * 128 + tid];

    int j = tid & 63;
    int kbase = (tid >> 6) << 6;
    const float4 rv = *(const float4*)(rel_attrs + (bi * 64 + j) * 4);
    __syncthreads();
    const float* vt = g_vt + b * (128 * 64);
#pragma unroll 4
    for (int kk = 0; kk < 64; kk++) {
        int k = kbase + kk;
        const float* w = re_w0 + k * 20;
        float val = Us[k] + vt[k * 64 + j] + rv.x * w[0] + rv.y * w[1] + rv.z * w[2] + rv.w * w[3];
        Hs[k * 64 + j] = fmaxf(val, 0.f);
    }

    // GEMM: out[j][f], 64x128x128, 8x8 micro-tiles
    int tx = tid & 15, ty = tid >> 4;
    int tx8 = tx * 8, ty8 = ty * 8;
    float acc[8][8];
#pragma unroll
    for (int i = 0; i < 8; i++)
#pragma unroll
        for (int q = 0; q < 8; q++) acc[i][q] = 0.f;

#pragma unroll 1
    for (int kc = 0; kc < 128; kc += 16) {
        __syncthreads();
#pragma unroll
        for (int r = 0; r < 16; r++) Wc[r * 128 + tid] = g_w1tre[(kc + r) * 128 + tid];
        __syncthreads();
#pragma unroll
        for (int k = 0; k < 16; k++) {
            float4 a0 = *(const float4*)&Hs[(kc + k) * 64 + ty8];
            float4 a1 = *(const float4*)&Hs[(kc + k) * 64 + ty8 + 4];
            float4 w0 = *(const float4*)&Wc[k * 128 + tx8];
            float4 w1 = *(const float4*)&Wc[k * 128 + tx8 + 4];
            float a[8] = {a0.x, a0.y, a0.z, a0.w, a1.x, a1.y, a1.z, a1.w};
            float w_[8] = {w0.x, w0.y, w0.z, w0.w, w1.x, w1.y, w1.z, w1.w};
#pragma unroll
            for (int jj = 0; jj < 8; jj++)
#pragma unroll
                for (int ff = 0; ff < 8; ff++) acc[jj][ff] += a[jj] * w_[ff];
        }
    }

    float* outp = g_rel + (long)bi * 8192;
#pragma unroll
    for (int ff = 0; ff < 8; ff++) {
        int f = tx8 + ff;
        float bb = re_b1[f];
        float4 o0 = make_float4(fmaxf(acc[0][ff] + bb, 0.f), fmaxf(acc[1][ff] + bb, 0.f),
                                fmaxf(acc[2][ff] + bb, 0.f), fmaxf(acc[3][ff] + bb, 0.f));
        float4 o1 = make_float4(fmaxf(acc[4][ff] + bb, 0.f), fmaxf(acc[5][ff] + bb, 0.f),
                                fmaxf(acc[6][ff] + bb, 0.f), fmaxf(acc[7][ff] + bb, 0.f));
        *(float4*)&outp[f * 64 + ty8] = o0;
        *(float4*)&outp[f * 64 + ty8 + 4] = o1;
    }
}

// ---------------- R/S precompute per step ----------------
__global__ void rs_kernel(const float* __restrict__ rp_b) {
    int node = blockIdx.x;
    int f = threadIdx.x;
    __shared__ float Os[128];
    Os[f] = g_obj[node * 128 + f];
    __syncthreads();
    float r = rp_b[f], s = 0.f;
#pragma unroll 8
    for (int k = 0; k < 128; k++) {
        float o = Os[k];
        r += g_wrecvt[k * 128 + f] * o;
        s += g_wsendt[k * 128 + f] * o;
    }
    g_R[node * 128 + f] = r;
    g_S[node * 128 + f] = s;
}

// ---------------- edge propagation: GEMM + LN + relu + sum over j ----------------
__global__ __launch_bounds__(128) void edge_prop_kernel(const float* __restrict__ rp_lnw,
                                                        const float* __restrict__ rp_lnb) {
    __shared__ float As[8192];     // [k][j] rel tile; reused as Ys[j][f] after GEMM
    __shared__ float Wc[16 * 128];
    __shared__ float Rs[128];
    __shared__ float Ps[512];
    int bi = blockIdx.x;
    int tid = threadIdx.x;
    int b = bi >> 6;
    Rs[tid] = g_R[bi * 128 + tid];
    const float* src = g_rel + (long)bi * 8192;
#pragma unroll 8
    for (int idx = tid; idx < 8192; idx += 128) As[idx] = src[idx];

    int tx = tid & 15, ty = tid >> 4;
    int tx8 = tx * 8, ty8 = ty * 8;
    float acc[8][8];
#pragma unroll
    for (int i = 0; i < 8; i++)
#pragma unroll
        for (int q = 0; q < 8; q++) acc[i][q] = 0.f;

#pragma unroll 1
    for (int kc = 0; kc < 128; kc += 16) {
        __syncthreads();
#pragma unroll
        for (int r = 0; r < 16; r++) Wc[r * 128 + tid] = g_wrt[(kc + r) * 128 + tid];
        __syncthreads();
#pragma unroll
        for (int k = 0; k < 16; k++) {
            float4 a0 = *(const float4*)&As[(kc + k) * 64 + ty8];
            float4 a1 = *(const float4*)&As[(kc + k) * 64 + ty8 + 4];
            float4 w0 = *(const float4*)&Wc[k * 128 + tx8];
            float4 w1 = *(const float4*)&Wc[k * 128 + tx8 + 4];
            float a[8] = {a0.x, a0.y, a0.z, a0.w, a1.x, a1.y, a1.z, a1.w};
            float w_[8] = {w0.x, w0.y, w0.z, w0.w, w1.x, w1.y, w1.z, w1.w};
#pragma unroll
            for (int jj = 0; jj < 8; jj++)
#pragma unroll
                for (int ff = 0; ff < 8; ff++) acc[jj][ff] += a[jj] * w_[ff];
        }
    }
    __syncthreads();  // all As reads done; safe to overwrite with Ys

    float4 R0 = *(const float4*)&Rs[tx8];
    float4 R1 = *(const float4*)&Rs[tx8 + 4];
#pragma unroll
    for (int jj = 0; jj < 8; jj++) {
        int j = ty8 + jj;
        const float* Sp = g_S + (b * 64 + j) * 128 + tx8;
        float4 s0 = *(const float4*)Sp;
        float4 s1 = *(const float4*)(Sp + 4);
        float4 y0 = make_float4(acc[jj][0] + R0.x + s0.x, acc[jj][1] + R0.y + s0.y,
                                acc[jj][2] + R0.z + s0.z, acc[jj][3] + R0.w + s0.w);
        float4 y1 = make_float4(acc[jj][4] + R1.x + s1.x, acc[jj][5] + R1.y + s1.y,
                                acc[jj][6] + R1.z + s1.z, acc[jj][7] + R1.w + s1.w);
        *(float4*)&As[j * 128 + tx8] = y0;
        *(float4*)&As[j * 128 + tx8 + 4] = y1;
    }
    __syncthreads();

    // LN per edge row, relu, aggregate over j (each warp owns 16 rows)
    int warp = tid >> 5, lane = tid & 31;
    float4 lw = *(const float4*)&rp_lnw[lane * 4];
    float4 lb = *(const float4*)&rp_lnb[lane * 4];
    float ag0 = 0.f, ag1 = 0.f, ag2 = 0.f, ag3 = 0.f;
#pragma unroll 4
    for (int r = 0; r < 16; r++) {
        int j = warp * 16 + r;
        float4 y = *(const float4*)&As[j * 128 + lane * 4];
        float s = y.x + y.y + y.z + y.w;
        float ss = y.x * y.x + y.y * y.y + y.z * y.z + y.w * y.w;
#pragma unroll
        for (int off = 16; off; off >>= 1) {
            s += __shfl_xor_sync(0xffffffffu, s, off);
            ss += __shfl_xor_sync(0xffffffffu, ss, off);
        }
        float mu = s * 0.0078125f;
        float var = ss * 0.0078125f - mu * mu;
        float rstd = rsqrtf(var + 1e-5f);
        ag0 += fmaxf((y.x - mu) * rstd * lw.x + lb.x, 0.f);
        ag1 += fmaxf((y.y - mu) * rstd * lw.y + lb.y, 0.f);
        ag2 += fmaxf((y.z - mu) * rstd * lw.z + lb.z, 0.f);
        ag3 += fmaxf((y.w - mu) * rstd * lw.w + lb.w, 0.f);
    }
    *(float4*)&Ps[warp * 128 + lane * 4] = make_float4(ag0, ag1, ag2, ag3);
    __syncthreads();
    g_agg[bi * 128 + tid] = Ps[tid] + Ps[128 + tid] + Ps[256 + tid] + Ps[384 + tid];
}

// ---------------- object update: [obj|agg](256) -> 128, LN, relu ----------------
__global__ void obj_update_kernel(const float* __restrict__ pp_b,
                                  const float* __restrict__ pp_lnw,
                                  const float* __restrict__ pp_lnb) {
    int node = blockIdx.x;
    int f = threadIdx.x;
    __shared__ float Xs[256];
    __shared__ float rs_[4], rss_[4];
    Xs[f] = g_obj[node * 128 + f];
    Xs[128 + f] = g_agg[node * 128 + f];
    __syncthreads();
    float acc = pp_b[f];
#pragma unroll 8
    for (int k = 0; k < 256; k++) acc += g_ppwt[k * 128 + f] * Xs[k];
    float s = acc, ss = acc * acc;
#pragma unroll
    for (int off = 16; off; off >>= 1) {
        s += __shfl_xor_sync(0xffffffffu, s, off);
        ss += __shfl_xor_sync(0xffffffffu, ss, off);
    }
    int warp = f >> 5, lane = f & 31;
    if (lane == 0) { rs_[warp] = s; rss_[warp] = ss; }
    __syncthreads();
    s = rs_[0] + rs_[1] + rs_[2] + rs_[3];
    ss = rss_[0] + rss_[1] + rss_[2] + rss_[3];
    float mu = s * 0.0078125f;
    float var = ss * 0.0078125f - mu * mu;
    float y = (acc - mu) * rsqrtf(var + 1e-5f) * pp_lnw[f] + pp_lnb[f];
    g_obj[node * 128 + f] = fmaxf(y, 0.f);
}

// ---------------- prediction head: 128 -> relu -> 32 -> tanh ----------------
__global__ void predict_kernel(const float* __restrict__ pr_b0,
                               const float* __restrict__ pr_b1,
                               float* __restrict__ out) {
    int node = blockIdx.x;
    int f = threadIdx.x;
    __shared__ float Os[128];
    __shared__ float Hs[128];
    Os[f] = g_obj[node * 128 + f];
    __syncthreads();
    float h = pr_b0[f];
#pragma unroll 8
    for (int k = 0; k < 128; k++) h += g_prw0t[k * 128 + f] * Os[k];
    Hs[f] = fmaxf(h, 0.f);
    __syncthreads();
    if (f < 32) {
        float o = pr_b1[f];
#pragma unroll 8
        for (int k = 0; k < 128; k++) o += g_prw1t[k * 32 + f] * Hs[k];
        out[node * 32 + f] = tanhf(o);
    }
}

// ---------------- launch ----------------
extern "C" void kernel_launch(void* const* d_in, const int* in_sizes, int n_in,
                              void* d_out, int out_size) {
    const float* attrs     = (const float*)d_in[0];
    const float* states    = (const float*)d_in[1];
    // d_in[2] = actions (unused, action=False path)
    const float* rel_attrs = (const float*)d_in[3];
    const float* oe_w0 = (const float*)d_in[4];
    const float* oe_b0 = (const float*)d_in[5];
    const float* oe_w1 = (const float*)d_in[6];
    const float* oe_b1 = (const float*)d_in[7];
    const float* re_w0 = (const float*)d_in[8];
    const float* re_b0 = (const float*)d_in[9];
    const float* re_w1 = (const float*)d_in[10];
    const float* re_b1 = (const float*)d_in[11];
    const float* rp_w  = (const float*)d_in[12];
    const float* rp_b  = (const float*)d_in[13];
    const float* rp_lnw = (const float*)d_in[14];
    const float* rp_lnb = (const float*)d_in[15];
    const float* pp_w  = (const float*)d_in[16];
    const float* pp_b  = (const float*)d_in[17];
    const float* pp_lnw = (const float*)d_in[18];
    const float* pp_lnb = (const float*)d_in[19];
    const float* pr_w0 = (const float*)d_in[20];
    const float* pr_b0 = (const float*)d_in[21];
    const float* pr_w1 = (const float*)d_in[22];
    const float* pr_b1 = (const float*)d_in[23];
    // d_in[24] = pstep (fixed at 2 in setup)
    float* out = (float*)d_out;

    prep_kernel<<<8, 256>>>(oe_w1, re_w1, rp_w, pp_w, pr_w0, pr_w1);
    node_pre_kernel<<<NNODES, 128>>>(attrs, states, re_w0, re_b0);
    obj_encode_kernel<<<NNODES, 128>>>(attrs, states, oe_w0, oe_b0, oe_b1);
    rel_encode_kernel<<<NNODES, 128>>>(rel_attrs, re_w0, re_b1);
    for (int step = 0; step < 2; step++) {
        rs_kernel<<<NNODES, 128>>>(rp_b);
        edge_prop_kernel<<<NNODES, 128>>>(rp_lnw, rp_lnb);
        obj_update_kernel<<<NNODES, 128>>>(pp_b, pp_lnw, pp_lnb);
    }
    predict_kernel<<<NNODES, 128>>>(pr_b0, pr_b1, out);
}

// round 2
// speedup vs baseline: 1.4208x; 1.4208x over previous
#include <cuda_runtime.h>
#include <math.h>

// Problem constants (fixed by setup_inputs)
// B=32, N=64, ATTR=4, STATE=8, REL=4, GDIM=32, NF=128, pstep=2
#define NNODES 2048            // B*N

// ---------------- scratch (static device memory; no allocations) ----------------
__device__ float g_E[2048 * 64 * 128];     // E = W_rel @ rel_encode, layout [bi][j][f] (64 MB)
__device__ float g_obj[2048 * 128];        // obj_encode (updated per step)
__device__ float g_u[2048 * 128];          // per-node recv part of re layer0 (incl b0)
__device__ float g_vt[32 * 128 * 64];      // per-node send part, layout [b][f][n]
__device__ float g_R[2048 * 128];          // W_recv @ obj + rp_b
__device__ float g_S[2048 * 128];          // W_send @ obj
__device__ float g_agg[2048 * 128];        // per-node aggregated edge effects
// transposed weights ([k][f] layouts for coalesced per-f accumulation)
__device__ float g_w1toe[128 * 128];
__device__ float g_w1tre[128 * 128];
__device__ float g_wrt[128 * 128];
__device__ float g_wrecvt[128 * 128];
__device__ float g_wsendt[128 * 128];
__device__ float g_ppwt[256 * 128];
__device__ float g_prw0t[128 * 128];
__device__ float g_prw1t[128 * 32];

// ---------------- weight prep: transposes ----------------
__global__ void prep_kernel(const float* __restrict__ oe_w1,
                            const float* __restrict__ re_w1,
                            const float* __restrict__ rp_w,
                            const float* __restrict__ pp_w,
                            const float* __restrict__ pr_w0,
                            const float* __restrict__ pr_w1) {
    int m = blockIdx.x;
    int t = threadIdx.x;
    if (m == 0) {
        for (int i = t; i < 128 * 128; i += 256) {
            int k = i >> 7, f = i & 127;
            g_w1toe[i] = oe_w1[f * 128 + k];
        }
    } else if (m == 1) {
        for (int i = t; i < 128 * 128; i += 256) {
            int k = i >> 7, f = i & 127;
            g_w1tre[i] = re_w1[f * 128 + k];
        }
    } else if (m == 2) {
        for (int i = t; i < 128 * 128; i += 256) {
            int k = i >> 7, f = i & 127;
            g_wrt[i] = rp_w[f * 384 + k];
        }
    } else if (m == 3) {
        for (int i = t; i < 128 * 128; i += 256) {
            int k = i >> 7, f = i & 127;
            g_wrecvt[i] = rp_w[f * 384 + 128 + k];
        }
    } else if (m == 4) {
        for (int i = t; i < 128 * 128; i += 256) {
            int k = i >> 7, f = i & 127;
            g_wsendt[i] = rp_w[f * 384 + 256 + k];
        }
    } else if (m == 5) {
        for (int i = t; i < 256 * 128; i += 256) {
            int k = i >> 7, f = i & 127;
            g_ppwt[i] = pp_w[f * 256 + k];
        }
    } else if (m == 6) {
        for (int i = t; i < 128 * 128; i += 256) {
            int k = i >> 7, f = i & 127;
            g_prw0t[i] = pr_w0[f * 128 + k];
        }
    } else {
        for (int i = t; i < 128 * 32; i += 256) {
            int k = i >> 5, o = i & 31;
            g_prw1t[i] = pr_w1[o * 128 + k];
        }
    }
}

// ---------------- per-node parts of rel layer0: u (recv) and v (send) ----------------
__global__ void node_pre_kernel(const float* __restrict__ attrs,
                                const float* __restrict__ states,
                                const float* __restrict__ re_w0,
                                const float* __restrict__ re_b0) {
    int node = blockIdx.x;
    int f = threadIdx.x;
    __shared__ float sa[4];
    __shared__ float ss[8];
    if (f < 4) sa[f] = attrs[node * 4 + f];
    if (f >= 4 && f < 12) ss[f - 4] = states[node * 8 + (f - 4)];
    __syncthreads();
    const float* w = re_w0 + f * 20;  // cols: [rel(4) | dstate(8) | recv_attr(4) | send_attr(4)]
    float u = re_b0[f];
    float v = 0.f;
#pragma unroll
    for (int c = 0; c < 8; c++) {
        float wc = w[4 + c];
        u += wc * ss[c];
        v -= wc * ss[c];
    }
#pragma unroll
    for (int c = 0; c < 4; c++) {
        u += w[12 + c] * sa[c];
        v += w[16 + c] * sa[c];
    }
    g_u[node * 128 + f] = u;
    int b = node >> 6, n = node & 63;
    g_vt[(b * 128 + f) * 64 + n] = v;
}

// ---------------- object encoder: 12 -> 128 -> 128, relu ----------------
__global__ void obj_encode_kernel(const float* __restrict__ attrs,
                                  const float* __restrict__ states,
                                  const float* __restrict__ oe_w0,
                                  const float* __restrict__ oe_b0,
                                  const float* __restrict__ oe_b1) {
    int node = blockIdx.x;
    int f = threadIdx.x;
    __shared__ float xs[12];
    __shared__ float hs[128];
    if (f < 4) xs[f] = attrs[node * 4 + f];
    if (f >= 4 && f < 12) xs[f] = states[node * 8 + (f - 4)];
    __syncthreads();
    const float* w = oe_w0 + f * 12;
    float h = oe_b0[f];
#pragma unroll
    for (int k = 0; k < 12; k++) h += w[k] * xs[k];
    hs[f] = fmaxf(h, 0.f);
    __syncthreads();
    float o = oe_b1[f];
#pragma unroll 16
    for (int k = 0; k < 128; k++) o += g_w1toe[k * 128 + f] * hs[k];
    g_obj[node * 128 + f] = fmaxf(o, 0.f);
}

// ---------------- fused relation encoder + edge-GEMM: per (b,i) block ----------------
// H[k][j]   = relu(W_rel . rel_attrs(b,i,j) + u[b,i][k] + v[b,j][k])          (128x64)
// rel[f][j] = relu(b1[f] + sum_k w1t[k][f] * H[k][j])                         (128x64, in smem)
// E[j][f']  = sum_k wrt[k][f'] * rel[k][j]      -> g_E [bi][j][f']            (64x128)
__global__ __launch_bounds__(128) void rel_fused_kernel(const float* __restrict__ rel_attrs,
                                                        const float* __restrict__ re_w0,
                                                        const float* __restrict__ re_b1) {
    __shared__ float Hs[8192];      // [k][j], reused as rel [f][j]
    __shared__ float Wc[2][2048];   // double-buffered 16x128 weight chunks
    __shared__ float Us[128];
    __shared__ float Bs[128];
    int bi = blockIdx.x;
    int tid = threadIdx.x;
    int b = bi >> 6;
    Us[tid] = g_u[bi * 128 + tid];
    Bs[tid] = re_b1[tid];

    int j = tid & 63;
    int kbase = (tid >> 6) << 6;
    const float4 rv = *(const float4*)(rel_attrs + (bi * 64 + j) * 4);
    __syncthreads();
    const float* vt = g_vt + b * (128 * 64);
#pragma unroll 4
    for (int kk = 0; kk < 64; kk++) {
        int k = kbase + kk;
        const float* w = re_w0 + k * 20;
        float val = Us[k] + vt[k * 64 + j] + rv.x * w[0] + rv.y * w[1] + rv.z * w[2] + rv.w * w[3];
        Hs[k * 64 + j] = fmaxf(val, 0.f);
    }

    // ---------- GEMM1: rel[f][j] = relu(b1 + W1t^T H).  tiles: 4 j x 16 f ----------
    {
        int tx = tid & 15;   // j group: j = 4*tx
        int ty = tid >> 4;   // f group: f = 16*ty
        float acc[4][16];
#pragma unroll
        for (int a = 0; a < 4; a++)
#pragma unroll
            for (int q = 0; q < 16; q++) acc[a][q] = 0.f;

        float4 st[4];
#pragma unroll
        for (int q = 0; q < 4; q++) st[q] = *(const float4*)&g_w1tre[q * 512 + tid * 4];
#pragma unroll
        for (int q = 0; q < 4; q++) *(float4*)&Wc[0][q * 512 + tid * 4] = st[q];
        __syncthreads();
        int p = 0;
#pragma unroll 1
        for (int kc = 0; kc < 128; kc += 16) {
            bool more = (kc + 16) < 128;
            if (more) {
#pragma unroll
                for (int q = 0; q < 4; q++)
                    st[q] = *(const float4*)&g_w1tre[(kc + 16) * 128 + q * 512 + tid * 4];
            }
            const float* cw = Wc[p];
#pragma unroll
            for (int k = 0; k < 16; k++) {
                float4 av = *(const float4*)&Hs[(kc + k) * 64 + tx * 4];
                float a[4] = {av.x, av.y, av.z, av.w};
                float w_[16];
#pragma unroll
                for (int q = 0; q < 4; q++) {
                    float4 wv = *(const float4*)&cw[k * 128 + ty * 16 + q * 4];
                    w_[q * 4] = wv.x; w_[q * 4 + 1] = wv.y; w_[q * 4 + 2] = wv.z; w_[q * 4 + 3] = wv.w;
                }
#pragma unroll
                for (int jj = 0; jj < 4; jj++)
#pragma unroll
                    for (int ff = 0; ff < 16; ff++) acc[jj][ff] += a[jj] * w_[ff];
            }
            if (more) {
#pragma unroll
                for (int q = 0; q < 4; q++) *(float4*)&Wc[p ^ 1][q * 512 + tid * 4] = st[q];
            }
            __syncthreads();
            p ^= 1;
        }
        // write rel into Hs as [f][j] (all H reads complete after final sync above)
#pragma unroll
        for (int ff = 0; ff < 16; ff++) {
            int f = ty * 16 + ff;
            float bb = Bs[f];
            float4 o = make_float4(fmaxf(acc[0][ff] + bb, 0.f), fmaxf(acc[1][ff] + bb, 0.f),
                                   fmaxf(acc[2][ff] + bb, 0.f), fmaxf(acc[3][ff] + bb, 0.f));
            *(float4*)&Hs[f * 64 + tx * 4] = o;
        }
    }
    __syncthreads();

    // ---------- GEMM2: E[j][f'] = Wrt^T rel.  tiles: 8 j x 8 f ----------
    {
        int tx = tid & 15;   // f' group: f' = 8*tx
        int ty = tid >> 4;   // j group:  j  = 8*ty
        int tx8 = tx * 8, ty8 = ty * 8;
        float acc[8][8];
#pragma unroll
        for (int a = 0; a < 8; a++)
#pragma unroll
            for (int q = 0; q < 8; q++) acc[a][q] = 0.f;

        float4 st[4];
#pragma unroll
        for (int q = 0; q < 4; q++) st[q] = *(const float4*)&g_wrt[q * 512 + tid * 4];
#pragma unroll
        for (int q = 0; q < 4; q++) *(float4*)&Wc[0][q * 512 + tid * 4] = st[q];
        __syncthreads();
        int p = 0;
#pragma unroll 1
        for (int kc = 0; kc < 128; kc += 16) {
            bool more = (kc + 16) < 128;
            if (more) {
#pragma unroll
                for (int q = 0; q < 4; q++)
                    st[q] = *(const float4*)&g_wrt[(kc + 16) * 128 + q * 512 + tid * 4];
            }
            const float* cw = Wc[p];
#pragma unroll
            for (int k = 0; k < 16; k++) {
                float4 a0 = *(const float4*)&Hs[(kc + k) * 64 + ty8];
                float4 a1 = *(const float4*)&Hs[(kc + k) * 64 + ty8 + 4];
                float4 w0 = *(const float4*)&cw[k * 128 + tx8];
                float4 w1 = *(const float4*)&cw[k * 128 + tx8 + 4];
                float a[8] = {a0.x, a0.y, a0.z, a0.w, a1.x, a1.y, a1.z, a1.w};
                float w_[8] = {w0.x, w0.y, w0.z, w0.w, w1.x, w1.y, w1.z, w1.w};
#pragma unroll
                for (int jj = 0; jj < 8; jj++)
#pragma unroll
                    for (int ff = 0; ff < 8; ff++) acc[jj][ff] += a[jj] * w_[ff];
            }
            if (more) {
#pragma unroll
                for (int q = 0; q < 4; q++) *(float4*)&Wc[p ^ 1][q * 512 + tid * 4] = st[q];
            }
            __syncthreads();
            p ^= 1;
        }
        float* outp = g_E + (long)bi * 8192;
#pragma unroll
        for (int jj = 0; jj < 8; jj++) {
            int jr = ty8 + jj;
            *(float4*)&outp[jr * 128 + tx8] =
                make_float4(acc[jj][0], acc[jj][1], acc[jj][2], acc[jj][3]);
            *(float4*)&outp[jr * 128 + tx8 + 4] =
                make_float4(acc[jj][4], acc[jj][5], acc[jj][6], acc[jj][7]);
        }
    }
}

// ---------------- R/S precompute per step ----------------
__global__ void rs_kernel(const float* __restrict__ rp_b) {
    int node = blockIdx.x;
    int f = threadIdx.x;
    __shared__ float Os[128];
    Os[f] = g_obj[node * 128 + f];
    __syncthreads();
    float r = rp_b[f], s = 0.f;
#pragma unroll 8
    for (int k = 0; k < 128; k++) {
        float o = Os[k];
        r += g_wrecvt[k * 128 + f] * o;
        s += g_wsendt[k * 128 + f] * o;
    }
    g_R[node * 128 + f] = r;
    g_S[node * 128 + f] = s;
}

// ---------------- edge apply: Y = E + R_i + S_j, LN, relu, sum over j ----------------
__global__ __launch_bounds__(128) void edge_apply_kernel(const float* __restrict__ rp_lnw,
                                                         const float* __restrict__ rp_lnb) {
    __shared__ float Rs[128];
    __shared__ float Ps[512];
    int bi = blockIdx.x;
    int tid = threadIdx.x;
    int b = bi >> 6;
    int warp = tid >> 5, lane = tid & 31;
    Rs[tid] = g_R[bi * 128 + tid];
    __syncthreads();
    float4 rv = *(const float4*)&Rs[lane * 4];
    float4 lw = *(const float4*)&rp_lnw[lane * 4];
    float4 lb = *(const float4*)&rp_lnb[lane * 4];
    const float* Ep = g_E + (long)bi * 8192;
    float ag0 = 0.f, ag1 = 0.f, ag2 = 0.f, ag3 = 0.f;
#pragma unroll 4
    for (int r = 0; r < 16; r++) {
        int j = warp * 16 + r;
        float4 e = *(const float4*)&Ep[j * 128 + lane * 4];
        float4 sv = *(const float4*)&g_S[(b * 64 + j) * 128 + lane * 4];
        float4 y = make_float4(e.x + rv.x + sv.x, e.y + rv.y + sv.y,
                               e.z + rv.z + sv.z, e.w + rv.w + sv.w);
        float s = y.x + y.y + y.z + y.w;
        float ss = y.x * y.x + y.y * y.y + y.z * y.z + y.w * y.w;
#pragma unroll
        for (int off = 16; off; off >>= 1) {
            s += __shfl_xor_sync(0xffffffffu, s, off);
            ss += __shfl_xor_sync(0xffffffffu, ss, off);
        }
        float mu = s * 0.0078125f;
        float var = ss * 0.0078125f - mu * mu;
        float rstd = rsqrtf(var + 1e-5f);
        ag0 += fmaxf((y.x - mu) * rstd * lw.x + lb.x, 0.f);
        ag1 += fmaxf((y.y - mu) * rstd * lw.y + lb.y, 0.f);
        ag2 += fmaxf((y.z - mu) * rstd * lw.z + lb.z, 0.f);
        ag3 += fmaxf((y.w - mu) * rstd * lw.w + lb.w, 0.f);
    }
    *(float4*)&Ps[warp * 128 + lane * 4] = make_float4(ag0, ag1, ag2, ag3);
    __syncthreads();
    g_agg[bi * 128 + tid] = Ps[tid] + Ps[128 + tid] + Ps[256 + tid] + Ps[384 + tid];
}

// ---------------- object update: [obj|agg](256) -> 128, LN, relu ----------------
__global__ void obj_update_kernel(const float* __restrict__ pp_b,
                                  const float* __restrict__ pp_lnw,
                                  const float* __restrict__ pp_lnb) {
    int node = blockIdx.x;
    int f = threadIdx.x;
    __shared__ float Xs[256];
    __shared__ float rs_[4], rss_[4];
    Xs[f] = g_obj[node * 128 + f];
    Xs[128 + f] = g_agg[node * 128 + f];
    __syncthreads();
    float acc = pp_b[f];
#pragma unroll 8
    for (int k = 0; k < 256; k++) acc += g_ppwt[k * 128 + f] * Xs[k];
    float s = acc, ss = acc * acc;
#pragma unroll
    for (int off = 16; off; off >>= 1) {
        s += __shfl_xor_sync(0xffffffffu, s, off);
        ss += __shfl_xor_sync(0xffffffffu, ss, off);
    }
    int warp = f >> 5, lane = f & 31;
    if (lane == 0) { rs_[warp] = s; rss_[warp] = ss; }
    __syncthreads();
    s = rs_[0] + rs_[1] + rs_[2] + rs_[3];
    ss = rss_[0] + rss_[1] + rss_[2] + rss_[3];
    float mu = s * 0.0078125f;
    float var = ss * 0.0078125f - mu * mu;
    float y = (acc - mu) * rsqrtf(var + 1e-5f) * pp_lnw[f] + pp_lnb[f];
    g_obj[node * 128 + f] = fmaxf(y, 0.f);
}

// ---------------- prediction head: 128 -> relu -> 32 -> tanh ----------------
__global__ void predict_kernel(const float* __restrict__ pr_b0,
                               const float* __restrict__ pr_b1,
                               float* __restrict__ out) {
    int node = blockIdx.x;
    int f = threadIdx.x;
    __shared__ float Os[128];
    __shared__ float Hs[128];
    Os[f] = g_obj[node * 128 + f];
    __syncthreads();
    float h = pr_b0[f];
#pragma unroll 8
    for (int k = 0; k < 128; k++) h += g_prw0t[k * 128 + f] * Os[k];
    Hs[f] = fmaxf(h, 0.f);
    __syncthreads();
    if (f < 32) {
        float o = pr_b1[f];
#pragma unroll 8
        for (int k = 0; k < 128; k++) o += g_prw1t[k * 32 + f] * Hs[k];
        out[node * 32 + f] = tanhf(o);
    }
}

// ---------------- launch ----------------
extern "C" void kernel_launch(void* const* d_in, const int* in_sizes, int n_in,
                              void* d_out, int out_size) {
    const float* attrs     = (const float*)d_in[0];
    const float* states    = (const float*)d_in[1];
    // d_in[2] = actions (unused, action=False path)
    const float* rel_attrs = (const float*)d_in[3];
    const float* oe_w0 = (const float*)d_in[4];
    const float* oe_b0 = (const float*)d_in[5];
    const float* oe_w1 = (const float*)d_in[6];
    const float* oe_b1 = (const float*)d_in[7];
    const float* re_w0 = (const float*)d_in[8];
    const float* re_b0 = (const float*)d_in[9];
    const float* re_w1 = (const float*)d_in[10];
    const float* re_b1 = (const float*)d_in[11];
    const float* rp_w  = (const float*)d_in[12];
    const float* rp_b  = (const float*)d_in[13];
    const float* rp_lnw = (const float*)d_in[14];
    const float* rp_lnb = (const float*)d_in[15];
    const float* pp_w  = (const float*)d_in[16];
    const float* pp_b  = (const float*)d_in[17];
    const float* pp_lnw = (const float*)d_in[18];
    const float* pp_lnb = (const float*)d_in[19];
    const float* pr_w0 = (const float*)d_in[20];
    const float* pr_b0 = (const float*)d_in[21];
    const float* pr_w1 = (const float*)d_in[22];
    const float* pr_b1 = (const float*)d_in[23];
    // d_in[24] = pstep (fixed at 2 in setup)
    float* out = (float*)d_out;

    prep_kernel<<<8, 256>>>(oe_w1, re_w1, rp_w, pp_w, pr_w0, pr_w1);
    node_pre_kernel<<<NNODES, 128>>>(attrs, states, re_w0, re_b0);
    obj_encode_kernel<<<NNODES, 128>>>(attrs, states, oe_w0, oe_b0, oe_b1);
    rel_fused_kernel<<<NNODES, 128>>>(rel_attrs, re_w0, re_b1);
    for (int step = 0; step < 2; step++) {
        rs_kernel<<<NNODES, 128>>>(rp_b);
        edge_apply_kernel<<<NNODES, 128>>>(rp_lnw, rp_lnb);
        obj_update_kernel<<<NNODES, 128>>>(pp_b, pp_lnw, pp_lnb);
    }
    predict_kernel<<<NNODES, 128>>>(pr_b0, pr_b1, out);
}